// round 15
// baseline (speedup 1.0000x reference)
#include <cuda_runtime.h>
#include <math.h>
#include <stdint.h>

#define BATCH 1024
#define IN_DIM 768
#define HID 1024
#define CLIP_D 512
#define NG 4
#define DS 64
#define DC 4
#define HD 64
#define DIN 2048
#define NH 32
#define CONV_DIM 2560
#define DINP 4640
#define DINP_P 4736
#define EPS 1e-5f

// ---------------- scratch (device globals) ----------------------------------
__device__ float g_wcat[2 * HID * IN_DIM];       // row-interleaved [wip_j; wig_j] tf32
__device__ float g_winproj_t[DINP_P * HID];
__device__ float g_woutproj_t[HID * DIN];
__device__ float g_woutgate_t[HID * HID];
__device__ float g_wproj_t[CLIP_D * HID];
__device__ float g_x_t[BATCH * IN_DIM];
__device__ float g_gated[BATCH * HID];
__device__ float g_gated_t[BATCH * HID];
__device__ float g_zx[BATCH * DINP_P];
__device__ float g_y_t[BATCH * DIN];
__device__ float g_outpre[BATCH * HID];
__device__ float g_outpre_t[BATCH * HID];
__device__ float g_out_t[BATCH * HID];

__device__ __forceinline__ float sigmoidf_(float x) { return 1.f / (1.f + expf(-x)); }
__device__ __forceinline__ float tf32r(float x) {
    uint32_t r;
    asm("cvt.rna.tf32.f32 %0, %1;" : "=r"(r) : "f"(x));
    return __uint_as_float(r);
}
__device__ __forceinline__ float4 tf32r4(float4 v) {
    return make_float4(tf32r(v.x), tf32r(v.y), tf32r(v.z), tf32r(v.w));
}

// ---------------- fused weight-conversion + LayerNorm kernel -----------------
#define R_WCAT  393216                 // 2048*768/4 (row-interleaved)
#define R_WINP  1212416                // 4736*256
#define R_WOP   524288
#define R_WOG   262144
#define R_WPJ   131072
#define R_TOTAL (R_WCAT + R_WINP + R_WOP + R_WOG + R_WPJ)
#define CVT_BLOCKS (R_TOTAL / 256)     // 9856 exactly

__global__ __launch_bounds__(256) void prep_k(const float4* __restrict__ wip,
                                              const float4* __restrict__ wig,
                                              const float4* __restrict__ winp,
                                              const float4* __restrict__ wop,
                                              const float4* __restrict__ wog,
                                              const float4* __restrict__ wpj,
                                              const float* __restrict__ frame_feat,
                                              const float* __restrict__ ln_w,
                                              const float* __restrict__ ln_b) {
    if (blockIdx.x >= BATCH) {
        int i = (blockIdx.x - BATCH) * 256 + threadIdx.x;
        float4 v = make_float4(0.f, 0.f, 0.f, 0.f);
        float4* dst;
        if (i < R_WCAT) {
            dst = (float4*)g_wcat + i;
            int row = i / 192, col = i - row * 192;
            int sr = (row >> 1) * 192 + col;
            v = (row & 1) ? wig[sr] : wip[sr];
        } else if (i < R_WCAT + R_WINP) {
            int j = i - R_WCAT;
            dst = (float4*)g_winproj_t + j;
            if ((j >> 8) < DINP) v = winp[j];
        } else if (i < R_WCAT + R_WINP + R_WOP) {
            int j = i - R_WCAT - R_WINP;
            dst = (float4*)g_woutproj_t + j;
            v = wop[j];
        } else if (i < R_WCAT + R_WINP + R_WOP + R_WOG) {
            int j = i - R_WCAT - R_WINP - R_WOP;
            dst = (float4*)g_woutgate_t + j;
            v = wog[j];
        } else {
            int j = i - R_WCAT - R_WINP - R_WOP - R_WOG;
            dst = (float4*)g_wproj_t + j;
            v = wpj[j];
        }
        *dst = tf32r4(v);
        return;
    }
    // LayerNorm rows
    int b = blockIdx.x, t = threadIdx.x;
    const float* row = frame_feat + (size_t)b * IN_DIM;
    float s = 0.f, s2 = 0.f;
    for (int i = t; i < IN_DIM; i += 256) { float v = row[i]; s += v; s2 += v * v; }
#pragma unroll
    for (int o = 16; o; o >>= 1) {
        s  += __shfl_xor_sync(0xffffffffu, s, o);
        s2 += __shfl_xor_sync(0xffffffffu, s2, o);
    }
    __shared__ float rs[8], rs2[8], stats[2];
    int wid = t >> 5, lane = t & 31;
    if (lane == 0) { rs[wid] = s; rs2[wid] = s2; }
    __syncthreads();
    if (t == 0) {
        float a = 0.f, a2 = 0.f;
        for (int i = 0; i < 8; i++) { a += rs[i]; a2 += rs2[i]; }
        float mu = a / IN_DIM;
        float var = a2 / IN_DIM - mu * mu;
        stats[0] = mu;
        stats[1] = rsqrtf(var + EPS);
    }
    __syncthreads();
    float mu = stats[0], inv = stats[1];
    for (int i = t; i < IN_DIM; i += 256)
        g_x_t[(size_t)b * IN_DIM + i] = tf32r((row[i] - mu) * inv * ln_w[i] + ln_b[i]);
}

// ---------------- tf32 tensor-core GEMM: swizzled smem, 3-stage --------------
// C[M,N] = A[M,K] @ B[N,K]^T.  BK=32, XOR-swizzle (seg ^= row&7), ldmatrix.
#define CP16(dst_s, src_g) \
    asm volatile("cp.async.cg.shared.global [%0], [%1], 16;" :: "r"(dst_s), "l"(src_g))

__device__ __forceinline__ void ldsm_x4(uint32_t* f, uint32_t a) {
    asm volatile("ldmatrix.sync.aligned.m8n8.x4.shared.b16 {%0,%1,%2,%3}, [%4];"
                 : "=r"(f[0]), "=r"(f[1]), "=r"(f[2]), "=r"(f[3]) : "r"(a));
}

template <int MODE, int BM, int BN, int MI, int NI, int NWARP>
__global__ __launch_bounds__(NWARP * 32, 2) void mma_gemm(const float* __restrict__ A,
                                                          const float* __restrict__ Bm,
                                                          float* __restrict__ C,
                                                          float* __restrict__ Ct,
                                                          int K, int N,
                                                          const float* __restrict__ bias,
                                                          const float* __restrict__ bias2,
                                                          const float* __restrict__ extra) {
    constexpr int WMC = BM / (16 * MI);           // warps along M
    constexpr int STG = (BM + BN) * 32;           // floats per stage (swizzled, no pad)
    constexpr int NTHR = NWARP * 32;

    extern __shared__ float sm[];
    const int tid = threadIdx.x, lane = tid & 31, wid = tid >> 5;
    const int r = lane >> 2, cl = lane & 3;
    const int MOFF = (wid % WMC) * MI * 16;
    const int NOFF = (wid / WMC) * NI * 8;
    const int m0 = blockIdx.y * BM, n0 = blockIdx.x * BN;
    const int iters = K >> 5;

    float acc[MI][NI][4];
#pragma unroll
    for (int mi = 0; mi < MI; mi++)
#pragma unroll
        for (int ni = 0; ni < NI; ni++)
#pragma unroll
            for (int j = 0; j < 4; j++) acc[mi][ni][j] = 0.f;

    // per-lane ldmatrix swizzle state (byte base + row&7 + k-half)
    const uint32_t sbase = (uint32_t)__cvta_generic_to_shared(sm);
    uint32_t a_base[MI], b_base[NI / 2];
    uint32_t a_r7[MI], b_r7[NI / 2];
    uint32_t a_kh, b_kh;
    {
        int am = lane >> 3, ai = lane & 7;
        a_kh = am >> 1;
#pragma unroll
        for (int mi = 0; mi < MI; mi++) {
            int row = MOFF + mi * 16 + (am & 1) * 8 + ai;
            a_base[mi] = (uint32_t)row * 128;       // row * 32 floats * 4 B
            a_r7[mi] = row & 7;
        }
        int bh = (lane >> 4) & 1, bk = (lane >> 3) & 1, bi = lane & 7;
        b_kh = bk;
#pragma unroll
        for (int j = 0; j < NI / 2; j++) {
            int row = BM + NOFF + j * 16 + bh * 8 + bi;
            b_base[j] = (uint32_t)row * 128;
            b_r7[j] = row & 7;
        }
    }

    auto load_tile = [&](int s, int kt) {
        float* base = sm + s * STG;
        int k0 = kt << 5;
#pragma unroll
        for (int it = 0; it < (BM + BN) * 8 / NTHR; it++) {
            int task = tid + it * NTHR;
            int row = task >> 3, seg = task & 7;
            const float* src = (row < BM)
                ? A + (size_t)(m0 + row) * K + k0 + (seg << 2)
                : Bm + (size_t)(n0 + row - BM) * K + k0 + (seg << 2);
            int ps = seg ^ (row & 7);
            uint32_t d = (uint32_t)__cvta_generic_to_shared(base + row * 32 + (ps << 2));
            CP16(d, src);
        }
        asm volatile("cp.async.commit_group;");
    };

    load_tile(0, 0);
    load_tile(1, 1);

    int s_cur = 0, s_nxt = 2;
    for (int kt = 0; kt < iters; kt++) {
        asm volatile("cp.async.wait_group 1;" ::: "memory");
        __syncthreads();
        if (kt + 2 < iters) load_tile(s_nxt, kt + 2);
        else asm volatile("cp.async.commit_group;");

        const uint32_t stage = sbase + (uint32_t)(s_cur * STG * 4);
#pragma unroll
        for (int kk = 0; kk < 4; kk++) {
            uint32_t af[MI][4], bf[NI][2];
#pragma unroll
            for (int mi = 0; mi < MI; mi++)
                ldsm_x4(af[mi], stage + a_base[mi] + ((((uint32_t)kk * 2 + a_kh) ^ a_r7[mi]) << 4));
#pragma unroll
            for (int j = 0; j < NI / 2; j++) {
                uint32_t tmp[4];
                ldsm_x4(tmp, stage + b_base[j] + ((((uint32_t)kk * 2 + b_kh) ^ b_r7[j]) << 4));
                bf[2 * j][0] = tmp[0]; bf[2 * j][1] = tmp[1];
                bf[2 * j + 1][0] = tmp[2]; bf[2 * j + 1][1] = tmp[3];
            }
#pragma unroll
            for (int mi = 0; mi < MI; mi++)
#pragma unroll
                for (int ni = 0; ni < NI; ni++) {
                    asm volatile(
                        "mma.sync.aligned.m16n8k8.row.col.f32.tf32.tf32.f32 "
                        "{%0,%1,%2,%3}, {%4,%5,%6,%7}, {%8,%9}, {%0,%1,%2,%3};"
                        : "+f"(acc[mi][ni][0]), "+f"(acc[mi][ni][1]),
                          "+f"(acc[mi][ni][2]), "+f"(acc[mi][ni][3])
                        : "r"(af[mi][0]), "r"(af[mi][1]), "r"(af[mi][2]), "r"(af[mi][3]),
                          "r"(bf[ni][0]), "r"(bf[ni][1]));
                }
        }
        s_cur = (s_cur == 2) ? 0 : s_cur + 1;
        s_nxt = (s_nxt == 2) ? 0 : s_nxt + 1;
    }

    // epilogue
#pragma unroll
    for (int mi = 0; mi < MI; mi++) {
        int row0 = m0 + MOFF + mi * 16 + r;
#pragma unroll
        for (int ni = 0; ni < NI; ni++) {
            int col = n0 + NOFF + ni * 8 + 2 * cl;
#pragma unroll
            for (int half = 0; half < 2; half++) {
                int row = row0 + half * 8;
                float v0 = acc[mi][ni][half * 2];
                float v1 = acc[mi][ni][half * 2 + 1];
                size_t off = (size_t)row * N + col;
                if (MODE == 0) {
                    *(float2*)(C + off) = make_float2(v0, v1);
                } else if (MODE == 1) {
                    float2 e = *(const float2*)(extra + off);
                    v0 += e.x; v1 += e.y;
                    *(float2*)(C + off) = make_float2(v0, v1);
                    *(float2*)(Ct + off) = make_float2(tf32r(v0), tf32r(v1));
                } else if (MODE == 2) {
                    float2 e = *(const float2*)(extra + off);
                    float o0 = e.x * sigmoidf_(v0 + bias[col]);
                    float o1 = e.y * sigmoidf_(v1 + bias[col + 1]);
                    *(float2*)(Ct + off) = make_float2(tf32r(o0), tf32r(o1));
                } else if (MODE == 3) {
                    *(float2*)(C + off) = make_float2(v0 + bias[col], v1 + bias[col + 1]);
                } else {  // MODE 4: interleaved gate pair
                    int j = col >> 1;
                    float g = (v0 + bias[j]) * sigmoidf_(v1 + bias2[j]);
                    size_t o = (size_t)row * HID + j;
                    C[o] = g;
                    Ct[o] = tf32r(g);
                }
            }
        }
    }
}

// ---------------- fused conv + SSM update + gated RMS norm -------------------
// unroll-2 SSM loop; __launch_bounds__(256, 8) pins regs <= 32 (8 CTAs/SM).
__global__ __launch_bounds__(256, 8) void state_kernel(const float* __restrict__ conv_state,
                                                       const float* __restrict__ ssm_state,
                                                       const float* __restrict__ conv_w,
                                                       const float* __restrict__ conv_b,
                                                       const float* __restrict__ A_log,
                                                       const float* __restrict__ Dp,
                                                       const float* __restrict__ dt_bias,
                                                       const float* __restrict__ norm_w,
                                                       float* __restrict__ out_conv,
                                                       float* __restrict__ out_ssm) {
    int b = blockIdx.x, t = threadIdx.x;
    __shared__ __align__(16) float s_act[CONV_DIM];
    __shared__ float s_dt[NH], s_dA[NH], s_dp[NH];
    __shared__ __align__(16) float s_y[DIN];
    __shared__ float s_part[8][NG];
    __shared__ float s_gsum[NG];

    const float* zx = g_zx + (size_t)b * DINP_P;

    if (t < NH) {
        float d = zx[DIN + CONV_DIM + t] + dt_bias[t];
        float dt = (d > 20.f) ? d : log1pf(expf(d));
        s_dt[t] = dt;
        s_dA[t] = expf(-expf(A_log[t]) * dt);
        s_dp[t] = Dp[t];
    }

    for (int c = t; c < CONV_DIM; c += 256) {
        float4 cs = __ldcs((const float4*)(conv_state + ((size_t)b * CONV_DIM + c) * 4));
        float xv = zx[DIN + c];
        float4 w4 = *(const float4*)(conv_w + (size_t)c * 4);
        float4 nc = make_float4(cs.y, cs.z, cs.w, xv);
        __stcs((float4*)(out_conv + ((size_t)b * CONV_DIM + c) * 4), nc);
        float s = nc.x * w4.x + nc.y * w4.y + nc.z * w4.z + nc.w * w4.w + conv_b[c];
        s_act[c] = s / (1.f + expf(-s));
    }
    __syncthreads();

    // SSM state update, unroll-2 for MLP (two loads in flight per thread)
    int lane16 = t & 15;
    int half = t >> 4;
#pragma unroll 1
    for (int it = 0; it < DIN / 16; it += 2) {
        int rr0 = it * 16 + half;
        int rr1 = rr0 + 16;
        int h0 = rr0 >> 6, p0 = rr0 & 63, g0 = h0 >> 3;
        int h1 = rr1 >> 6, p1 = rr1 & 63, g1 = h1 >> 3;
        size_t base0 = (((size_t)b * NH + h0) * HD + p0) * DS + lane16 * 4;
        size_t base1 = (((size_t)b * NH + h1) * HD + p1) * DS + lane16 * 4;
        float4 sv0 = __ldcs((const float4*)(ssm_state + base0));
        float4 sv1 = __ldcs((const float4*)(ssm_state + base1));

        float4 B40 = *(const float4*)&s_act[DIN + g0 * DS + lane16 * 4];
        float4 C40 = *(const float4*)&s_act[DIN + NG * DS + g0 * DS + lane16 * 4];
        float xh0 = s_act[h0 * HD + p0];
        float coef0 = s_dt[h0] * xh0;
        float dA0 = s_dA[h0];
        float4 ns0;
        ns0.x = sv0.x * dA0 + coef0 * B40.x;
        ns0.y = sv0.y * dA0 + coef0 * B40.y;
        ns0.z = sv0.z * dA0 + coef0 * B40.z;
        ns0.w = sv0.w * dA0 + coef0 * B40.w;
        __stcs((float4*)(out_ssm + base0), ns0);
        float part0 = ns0.x * C40.x + ns0.y * C40.y + ns0.z * C40.z + ns0.w * C40.w;

        float4 B41 = *(const float4*)&s_act[DIN + g1 * DS + lane16 * 4];
        float4 C41 = *(const float4*)&s_act[DIN + NG * DS + g1 * DS + lane16 * 4];
        float xh1 = s_act[h1 * HD + p1];
        float coef1 = s_dt[h1] * xh1;
        float dA1 = s_dA[h1];
        float4 ns1;
        ns1.x = sv1.x * dA1 + coef1 * B41.x;
        ns1.y = sv1.y * dA1 + coef1 * B41.y;
        ns1.z = sv1.z * dA1 + coef1 * B41.z;
        ns1.w = sv1.w * dA1 + coef1 * B41.w;
        __stcs((float4*)(out_ssm + base1), ns1);
        float part1 = ns1.x * C41.x + ns1.y * C41.y + ns1.z * C41.z + ns1.w * C41.w;

#pragma unroll
        for (int o = 8; o; o >>= 1) {
            part0 += __shfl_xor_sync(0xffffffffu, part0, o, 16);
            part1 += __shfl_xor_sync(0xffffffffu, part1, o, 16);
        }
        if (lane16 == 0) {
            s_y[rr0] = part0 + s_dp[h0] * xh0;
            s_y[rr1] = part1 + s_dp[h1] * xh1;
        }
    }
    __syncthreads();

    float lsum[4] = {0.f, 0.f, 0.f, 0.f};
#pragma unroll
    for (int k = 0; k < 8; k++) {
        int d = t + k * 256;
        float z = zx[d];
        float yv = s_y[d] * (z / (1.f + expf(-z)));
        s_y[d] = yv;
        lsum[k >> 1] += yv * yv;
    }
    int wid = t >> 5, lane = t & 31;
#pragma unroll
    for (int gg = 0; gg < NG; gg++) {
        float v = lsum[gg];
#pragma unroll
        for (int o = 16; o; o >>= 1) v += __shfl_xor_sync(0xffffffffu, v, o);
        if (lane == 0) s_part[wid][gg] = v;
    }
    __syncthreads();
    if (t < NG) {
        float a = 0.f;
        for (int w = 0; w < 8; w++) a += s_part[w][t];
        s_gsum[t] = a;
    }
    __syncthreads();
#pragma unroll
    for (int k = 0; k < 8; k++) {
        int d = t + k * 256;
        float scale = rsqrtf(s_gsum[k >> 1] * (1.f / 512.f) + EPS);
        g_y_t[(size_t)b * DIN + d] = tf32r(s_y[d] * scale * norm_w[d]);
    }
}

// ---------------- launch ----------------------------------------------------
#define SMEM_BIG3 (3 * (128 + 128) * 32 * 4)   // 98304
#define SMEM_MED3 (3 * (128 + 64) * 32 * 4)    // 73728
#define SMEM_SML3 (3 * (64 + 64) * 32 * 4)     // 49152

extern "C" void kernel_launch(void* const* d_in, const int* in_sizes, int n_in,
                              void* d_out, int out_size) {
    const float* frame_feat   = (const float*)d_in[0];
    const float* conv_state   = (const float*)d_in[1];
    const float* ssm_state    = (const float*)d_in[2];
    const float* ln_w         = (const float*)d_in[3];
    const float* ln_b         = (const float*)d_in[4];
    const float* w_in_gate    = (const float*)d_in[5];
    const float* b_in_gate    = (const float*)d_in[6];
    const float* w_input_proj = (const float*)d_in[7];
    const float* b_input_proj = (const float*)d_in[8];
    const float* w_in_proj    = (const float*)d_in[9];
    const float* conv_w       = (const float*)d_in[10];
    const float* conv_b       = (const float*)d_in[11];
    const float* A_log        = (const float*)d_in[12];
    const float* Dp           = (const float*)d_in[13];
    const float* dt_bias      = (const float*)d_in[14];
    const float* norm_w       = (const float*)d_in[15];
    const float* w_out_proj   = (const float*)d_in[16];
    const float* w_out_gate   = (const float*)d_in[17];
    const float* b_out_gate   = (const float*)d_in[18];
    const float* w_proj       = (const float*)d_in[19];
    const float* b_proj       = (const float*)d_in[20];

    float* out = (float*)d_out;
    float* out_clip = out;
    float* out_conv = out + (size_t)BATCH * CLIP_D;
    float* out_ssm = out_conv + (size_t)BATCH * CONV_DIM * DC;

    float *p_wcat, *p_winp, *p_wop, *p_wog, *p_wpj;
    float *p_xt, *p_gated, *p_gated_t, *p_zx, *p_yt, *p_op, *p_opt, *p_ot;
    cudaGetSymbolAddress((void**)&p_wcat, g_wcat);
    cudaGetSymbolAddress((void**)&p_winp, g_winproj_t);
    cudaGetSymbolAddress((void**)&p_wop, g_woutproj_t);
    cudaGetSymbolAddress((void**)&p_wog, g_woutgate_t);
    cudaGetSymbolAddress((void**)&p_wpj, g_wproj_t);
    cudaGetSymbolAddress((void**)&p_xt, g_x_t);
    cudaGetSymbolAddress((void**)&p_gated, g_gated);
    cudaGetSymbolAddress((void**)&p_gated_t, g_gated_t);
    cudaGetSymbolAddress((void**)&p_zx, g_zx);
    cudaGetSymbolAddress((void**)&p_yt, g_y_t);
    cudaGetSymbolAddress((void**)&p_op, g_outpre);
    cudaGetSymbolAddress((void**)&p_opt, g_outpre_t);
    cudaGetSymbolAddress((void**)&p_ot, g_out_t);

    cudaFuncSetAttribute((mma_gemm<4, 128, 128, 4, 8, 4>), cudaFuncAttributeMaxDynamicSharedMemorySize, SMEM_BIG3);
    cudaFuncSetAttribute((mma_gemm<0, 128, 128, 4, 8, 4>), cudaFuncAttributeMaxDynamicSharedMemorySize, SMEM_BIG3);
    cudaFuncSetAttribute((mma_gemm<1, 128, 64, 2, 4, 8>), cudaFuncAttributeMaxDynamicSharedMemorySize, SMEM_MED3);
    cudaFuncSetAttribute((mma_gemm<2, 128, 64, 2, 4, 8>), cudaFuncAttributeMaxDynamicSharedMemorySize, SMEM_MED3);
    cudaFuncSetAttribute((mma_gemm<3, 64, 64, 2, 2, 8>), cudaFuncAttributeMaxDynamicSharedMemorySize, SMEM_SML3);

    // 0) LayerNorm (first blocks) + weight conversions, one launch
    prep_k<<<BATCH + CVT_BLOCKS, 256>>>((const float4*)w_input_proj,
                                        (const float4*)w_in_gate,
                                        (const float4*)w_in_proj,
                                        (const float4*)w_out_proj,
                                        (const float4*)w_out_gate,
                                        (const float4*)w_proj,
                                        frame_feat, ln_w, ln_b);

    // 2) gate pair GEMM — BIG tile, 4 warps (64x64 warp tile), interleaved epilogue
    mma_gemm<4, 128, 128, 4, 8, 4><<<dim3(2048 / 128, BATCH / 128), 128, SMEM_BIG3>>>(
        p_xt, p_wcat, p_gated, p_gated_t, IN_DIM, 2048, b_input_proj, b_in_gate, nullptr);

    // 3) zx = gated @ w_in_proj^T (padded N) — BIG tile, 4 warps
    mma_gemm<0, 128, 128, 4, 8, 4><<<dim3(DINP_P / 128, BATCH / 128), 128, SMEM_BIG3>>>(
        p_gated_t, p_winp, p_zx, nullptr, HID, DINP_P, nullptr, nullptr, nullptr);

    // 4) conv + ssm + rmsnorm
    state_kernel<<<BATCH, 256>>>(conv_state, ssm_state, conv_w, conv_b,
                                 A_log, Dp, dt_bias, norm_w, out_conv, out_ssm);

    // 5) outpre = y @ w_out_proj^T + gated — MED tile, 8 warps, 3-stage
    mma_gemm<1, 128, 64, 2, 4, 8><<<dim3(HID / 64, BATCH / 128), 256, SMEM_MED3>>>(
        p_yt, p_wop, p_op, p_opt, DIN, HID, nullptr, nullptr, p_gated);

    // 6) out = outpre * sigmoid(outpre @ w_out_gate^T + b) — MED tile, 8 warps, 3-stage
    mma_gemm<2, 128, 64, 2, 4, 8><<<dim3(HID / 64, BATCH / 128), 256, SMEM_MED3>>>(
        p_opt, p_wog, nullptr, p_ot, HID, HID, b_out_gate, nullptr, p_op);

    // 7) clip = out @ w_proj^T + b — SML tile, 8 warps, 3-stage
    mma_gemm<3, 64, 64, 2, 2, 8><<<dim3(CLIP_D / 64, BATCH / 64), 256, SMEM_SML3>>>(
        p_ot, p_wpj, out_clip, nullptr, HID, CLIP_D, b_proj, nullptr, nullptr);
}

// round 16
// speedup vs baseline: 1.2182x; 1.2182x over previous
#include <cuda_runtime.h>
#include <cuda_fp16.h>
#include <math.h>
#include <stdint.h>

#define BATCH 1024
#define IN_DIM 768
#define HID 1024
#define CLIP_D 512
#define NG 4
#define DS 64
#define DC 4
#define HD 64
#define DIN 2048
#define NH 32
#define CONV_DIM 2560
#define DINP 4640
#define DINP_P 4736
#define EPS 1e-5f

// ---------------- scratch (device globals) ----------------------------------
// GEMM operand buffers in fp16; zx / gated / outpre stay fp32.
__device__ __half g_wcat[2 * HID * IN_DIM];     // row-interleaved [wip_j; wig_j]
__device__ __half g_winproj_h[DINP_P * HID];
__device__ __half g_woutproj_h[HID * DIN];
__device__ __half g_woutgate_h[HID * HID];
__device__ __half g_wproj_h[CLIP_D * HID];
__device__ __half g_x_h[BATCH * IN_DIM];
__device__ float  g_gated[BATCH * HID];
__device__ __half g_gated_h[BATCH * HID];
__device__ float  g_zx[BATCH * DINP_P];
__device__ __half g_y_h[BATCH * DIN];
__device__ float  g_outpre[BATCH * HID];
__device__ __half g_outpre_h[BATCH * HID];
__device__ __half g_out_h[BATCH * HID];

__device__ __forceinline__ float sigmoidf_(float x) { return 1.f / (1.f + expf(-x)); }

__device__ __forceinline__ void st_half4(__half* p, float4 v) {
    __half2 lo = __floats2half2_rn(v.x, v.y);
    __half2 hi = __floats2half2_rn(v.z, v.w);
    uint2 u;
    u.x = *(uint32_t*)&lo;
    u.y = *(uint32_t*)&hi;
    *(uint2*)p = u;
}

// ---------------- fused weight-conversion + LayerNorm kernel -----------------
#define R_WCAT  393216                 // 2048*768/4 (row-interleaved)
#define R_WINP  1212416                // 4736*256
#define R_WOP   524288
#define R_WOG   262144
#define R_WPJ   131072
#define R_TOTAL (R_WCAT + R_WINP + R_WOP + R_WOG + R_WPJ)
#define CVT_BLOCKS (R_TOTAL / 256)     // 9856 exactly

__global__ __launch_bounds__(256) void prep_k(const float4* __restrict__ wip,
                                              const float4* __restrict__ wig,
                                              const float4* __restrict__ winp,
                                              const float4* __restrict__ wop,
                                              const float4* __restrict__ wog,
                                              const float4* __restrict__ wpj,
                                              const float* __restrict__ frame_feat,
                                              const float* __restrict__ ln_w,
                                              const float* __restrict__ ln_b) {
    if (blockIdx.x >= BATCH) {
        int i = (blockIdx.x - BATCH) * 256 + threadIdx.x;
        float4 v = make_float4(0.f, 0.f, 0.f, 0.f);
        __half* dst;
        if (i < R_WCAT) {
            dst = g_wcat + (size_t)i * 4;
            int row = i / 192, col = i - row * 192;
            int sr = (row >> 1) * 192 + col;
            v = (row & 1) ? wig[sr] : wip[sr];
        } else if (i < R_WCAT + R_WINP) {
            int j = i - R_WCAT;
            dst = g_winproj_h + (size_t)j * 4;
            if ((j >> 8) < DINP) v = winp[j];
        } else if (i < R_WCAT + R_WINP + R_WOP) {
            int j = i - R_WCAT - R_WINP;
            dst = g_woutproj_h + (size_t)j * 4;
            v = wop[j];
        } else if (i < R_WCAT + R_WINP + R_WOP + R_WOG) {
            int j = i - R_WCAT - R_WINP - R_WOP;
            dst = g_woutgate_h + (size_t)j * 4;
            v = wog[j];
        } else {
            int j = i - R_WCAT - R_WINP - R_WOP - R_WOG;
            dst = g_wproj_h + (size_t)j * 4;
            v = wpj[j];
        }
        st_half4(dst, v);
        return;
    }
    // LayerNorm rows
    int b = blockIdx.x, t = threadIdx.x;
    const float* row = frame_feat + (size_t)b * IN_DIM;
    float s = 0.f, s2 = 0.f;
    for (int i = t; i < IN_DIM; i += 256) { float v = row[i]; s += v; s2 += v * v; }
#pragma unroll
    for (int o = 16; o; o >>= 1) {
        s  += __shfl_xor_sync(0xffffffffu, s, o);
        s2 += __shfl_xor_sync(0xffffffffu, s2, o);
    }
    __shared__ float rs[8], rs2[8], stats[2];
    int wid = t >> 5, lane = t & 31;
    if (lane == 0) { rs[wid] = s; rs2[wid] = s2; }
    __syncthreads();
    if (t == 0) {
        float a = 0.f, a2 = 0.f;
        for (int i = 0; i < 8; i++) { a += rs[i]; a2 += rs2[i]; }
        float mu = a / IN_DIM;
        float var = a2 / IN_DIM - mu * mu;
        stats[0] = mu;
        stats[1] = rsqrtf(var + EPS);
    }
    __syncthreads();
    float mu = stats[0], inv = stats[1];
    for (int i = t; i < IN_DIM; i += 256)
        g_x_h[(size_t)b * IN_DIM + i] = __float2half_rn((row[i] - mu) * inv * ln_w[i] + ln_b[i]);
}

// ---------------- fp16 tensor-core GEMM: swizzled smem, 3-stage --------------
// C[M,N] = A[M,K] @ B[N,K]^T, fp16 operands, fp32 accum.
// BK=64 halves (128 B/row, 8x16B segs — same byte geometry as tf32 BK=32),
// XOR-swizzle (seg ^= row&7), ldmatrix b16, mma.m16n8k16.f16.
#define CP16(dst_s, src_g) \
    asm volatile("cp.async.cg.shared.global [%0], [%1], 16;" :: "r"(dst_s), "l"(src_g))

__device__ __forceinline__ void ldsm_x4(uint32_t* f, uint32_t a) {
    asm volatile("ldmatrix.sync.aligned.m8n8.x4.shared.b16 {%0,%1,%2,%3}, [%4];"
                 : "=r"(f[0]), "=r"(f[1]), "=r"(f[2]), "=r"(f[3]) : "r"(a));
}

template <int MODE, int BM, int BN, int MI, int NI, int NWARP>
__global__ __launch_bounds__(NWARP * 32, 2) void mma_gemm(const __half* __restrict__ A,
                                                          const __half* __restrict__ Bm,
                                                          float* __restrict__ C,
                                                          __half* __restrict__ Ct,
                                                          int K, int N,
                                                          const float* __restrict__ bias,
                                                          const float* __restrict__ bias2,
                                                          const float* __restrict__ extra) {
    constexpr int WMC = BM / (16 * MI);           // warps along M
    constexpr int STG = (BM + BN) * 64;           // halves per stage (128 B/row)
    constexpr int NTHR = NWARP * 32;

    extern __shared__ __half smh[];
    const int tid = threadIdx.x, lane = tid & 31, wid = tid >> 5;
    const int r = lane >> 2, cl = lane & 3;
    const int MOFF = (wid % WMC) * MI * 16;
    const int NOFF = (wid / WMC) * NI * 8;
    const int m0 = blockIdx.y * BM, n0 = blockIdx.x * BN;
    const int iters = K >> 6;                     // BK = 64 halves

    float acc[MI][NI][4];
#pragma unroll
    for (int mi = 0; mi < MI; mi++)
#pragma unroll
        for (int ni = 0; ni < NI; ni++)
#pragma unroll
            for (int j = 0; j < 4; j++) acc[mi][ni][j] = 0.f;

    // per-lane ldmatrix swizzle state (byte base + row&7 + k-half) — byte
    // geometry identical to the tf32 version (row = 128 bytes, 8 segs).
    const uint32_t sbase = (uint32_t)__cvta_generic_to_shared(smh);
    uint32_t a_base[MI], b_base[NI / 2];
    uint32_t a_r7[MI], b_r7[NI / 2];
    uint32_t a_kh, b_kh;
    {
        int am = lane >> 3, ai = lane & 7;
        a_kh = am >> 1;
#pragma unroll
        for (int mi = 0; mi < MI; mi++) {
            int row = MOFF + mi * 16 + (am & 1) * 8 + ai;
            a_base[mi] = (uint32_t)row * 128;     // bytes
            a_r7[mi] = row & 7;
        }
        int bh = (lane >> 4) & 1, bk = (lane >> 3) & 1, bi = lane & 7;
        b_kh = bk;
#pragma unroll
        for (int j = 0; j < NI / 2; j++) {
            int row = BM + NOFF + j * 16 + bh * 8 + bi;
            b_base[j] = (uint32_t)row * 128;
            b_r7[j] = row & 7;
        }
    }

    auto load_tile = [&](int s, int kt) {
        __half* base = smh + s * STG;
        int k0 = kt << 6;
#pragma unroll
        for (int it = 0; it < (BM + BN) * 8 / NTHR; it++) {
            int task = tid + it * NTHR;
            int row = task >> 3, seg = task & 7;
            const __half* src = (row < BM)
                ? A + (size_t)(m0 + row) * K + k0 + (seg << 3)
                : Bm + (size_t)(n0 + row - BM) * K + k0 + (seg << 3);
            int ps = seg ^ (row & 7);
            uint32_t d = (uint32_t)__cvta_generic_to_shared(base + row * 64 + (ps << 3));
            CP16(d, src);
        }
        asm volatile("cp.async.commit_group;");
    };

    load_tile(0, 0);
    load_tile(1, 1);

    int s_cur = 0, s_nxt = 2;
    for (int kt = 0; kt < iters; kt++) {
        asm volatile("cp.async.wait_group 1;" ::: "memory");
        __syncthreads();
        if (kt + 2 < iters) load_tile(s_nxt, kt + 2);
        else asm volatile("cp.async.commit_group;");

        const uint32_t stage = sbase + (uint32_t)(s_cur * STG * 2);
#pragma unroll
        for (int kk = 0; kk < 4; kk++) {          // 4 x k16 chunks = 64 halves
            uint32_t af[MI][4], bf[NI][2];
#pragma unroll
            for (int mi = 0; mi < MI; mi++)
                ldsm_x4(af[mi], stage + a_base[mi] + ((((uint32_t)kk * 2 + a_kh) ^ a_r7[mi]) << 4));
#pragma unroll
            for (int j = 0; j < NI / 2; j++) {
                uint32_t tmp[4];
                ldsm_x4(tmp, stage + b_base[j] + ((((uint32_t)kk * 2 + b_kh) ^ b_r7[j]) << 4));
                bf[2 * j][0] = tmp[0]; bf[2 * j][1] = tmp[1];
                bf[2 * j + 1][0] = tmp[2]; bf[2 * j + 1][1] = tmp[3];
            }
#pragma unroll
            for (int mi = 0; mi < MI; mi++)
#pragma unroll
                for (int ni = 0; ni < NI; ni++) {
                    asm volatile(
                        "mma.sync.aligned.m16n8k16.row.col.f32.f16.f16.f32 "
                        "{%0,%1,%2,%3}, {%4,%5,%6,%7}, {%8,%9}, {%0,%1,%2,%3};"
                        : "+f"(acc[mi][ni][0]), "+f"(acc[mi][ni][1]),
                          "+f"(acc[mi][ni][2]), "+f"(acc[mi][ni][3])
                        : "r"(af[mi][0]), "r"(af[mi][1]), "r"(af[mi][2]), "r"(af[mi][3]),
                          "r"(bf[ni][0]), "r"(bf[ni][1]));
                }
        }
        s_cur = (s_cur == 2) ? 0 : s_cur + 1;
        s_nxt = (s_nxt == 2) ? 0 : s_nxt + 1;
    }

    // epilogue
#pragma unroll
    for (int mi = 0; mi < MI; mi++) {
        int row0 = m0 + MOFF + mi * 16 + r;
#pragma unroll
        for (int ni = 0; ni < NI; ni++) {
            int col = n0 + NOFF + ni * 8 + 2 * cl;
#pragma unroll
            for (int half = 0; half < 2; half++) {
                int row = row0 + half * 8;
                float v0 = acc[mi][ni][half * 2];
                float v1 = acc[mi][ni][half * 2 + 1];
                size_t off = (size_t)row * N + col;
                if (MODE == 0) {
                    *(float2*)(C + off) = make_float2(v0, v1);
                } else if (MODE == 1) {
                    float2 e = *(const float2*)(extra + off);
                    v0 += e.x; v1 += e.y;
                    *(float2*)(C + off) = make_float2(v0, v1);
                    *(__half2*)(Ct + off) = __floats2half2_rn(v0, v1);
                } else if (MODE == 2) {
                    float2 e = *(const float2*)(extra + off);
                    float o0 = e.x * sigmoidf_(v0 + bias[col]);
                    float o1 = e.y * sigmoidf_(v1 + bias[col + 1]);
                    *(__half2*)(Ct + off) = __floats2half2_rn(o0, o1);
                } else if (MODE == 3) {
                    *(float2*)(C + off) = make_float2(v0 + bias[col], v1 + bias[col + 1]);
                } else {  // MODE 4: interleaved gate pair
                    int j = col >> 1;
                    float g = (v0 + bias[j]) * sigmoidf_(v1 + bias2[j]);
                    size_t o = (size_t)row * HID + j;
                    C[o] = g;
                    Ct[o] = __float2half_rn(g);
                }
            }
        }
    }
}

// ---------------- fused conv + SSM update + gated RMS norm -------------------
// unroll-2 SSM loop; __launch_bounds__(256, 8) pins regs <= 32 (8 CTAs/SM).
__global__ __launch_bounds__(256, 8) void state_kernel(const float* __restrict__ conv_state,
                                                       const float* __restrict__ ssm_state,
                                                       const float* __restrict__ conv_w,
                                                       const float* __restrict__ conv_b,
                                                       const float* __restrict__ A_log,
                                                       const float* __restrict__ Dp,
                                                       const float* __restrict__ dt_bias,
                                                       const float* __restrict__ norm_w,
                                                       float* __restrict__ out_conv,
                                                       float* __restrict__ out_ssm) {
    int b = blockIdx.x, t = threadIdx.x;
    __shared__ __align__(16) float s_act[CONV_DIM];
    __shared__ float s_dt[NH], s_dA[NH], s_dp[NH];
    __shared__ __align__(16) float s_y[DIN];
    __shared__ float s_part[8][NG];
    __shared__ float s_gsum[NG];

    const float* zx = g_zx + (size_t)b * DINP_P;

    if (t < NH) {
        float d = zx[DIN + CONV_DIM + t] + dt_bias[t];
        float dt = (d > 20.f) ? d : log1pf(expf(d));
        s_dt[t] = dt;
        s_dA[t] = expf(-expf(A_log[t]) * dt);
        s_dp[t] = Dp[t];
    }

    for (int c = t; c < CONV_DIM; c += 256) {
        float4 cs = __ldcs((const float4*)(conv_state + ((size_t)b * CONV_DIM + c) * 4));
        float xv = zx[DIN + c];
        float4 w4 = *(const float4*)(conv_w + (size_t)c * 4);
        float4 nc = make_float4(cs.y, cs.z, cs.w, xv);
        __stcs((float4*)(out_conv + ((size_t)b * CONV_DIM + c) * 4), nc);
        float s = nc.x * w4.x + nc.y * w4.y + nc.z * w4.z + nc.w * w4.w + conv_b[c];
        s_act[c] = s / (1.f + expf(-s));
    }
    __syncthreads();

    // SSM state update, unroll-2 for MLP (two loads in flight per thread)
    int lane16 = t & 15;
    int half = t >> 4;
#pragma unroll 1
    for (int it = 0; it < DIN / 16; it += 2) {
        int rr0 = it * 16 + half;
        int rr1 = rr0 + 16;
        int h0 = rr0 >> 6, p0 = rr0 & 63, g0 = h0 >> 3;
        int h1 = rr1 >> 6, p1 = rr1 & 63, g1 = h1 >> 3;
        size_t base0 = (((size_t)b * NH + h0) * HD + p0) * DS + lane16 * 4;
        size_t base1 = (((size_t)b * NH + h1) * HD + p1) * DS + lane16 * 4;
        float4 sv0 = __ldcs((const float4*)(ssm_state + base0));
        float4 sv1 = __ldcs((const float4*)(ssm_state + base1));

        float4 B40 = *(const float4*)&s_act[DIN + g0 * DS + lane16 * 4];
        float4 C40 = *(const float4*)&s_act[DIN + NG * DS + g0 * DS + lane16 * 4];
        float xh0 = s_act[h0 * HD + p0];
        float coef0 = s_dt[h0] * xh0;
        float dA0 = s_dA[h0];
        float4 ns0;
        ns0.x = sv0.x * dA0 + coef0 * B40.x;
        ns0.y = sv0.y * dA0 + coef0 * B40.y;
        ns0.z = sv0.z * dA0 + coef0 * B40.z;
        ns0.w = sv0.w * dA0 + coef0 * B40.w;
        __stcs((float4*)(out_ssm + base0), ns0);
        float part0 = ns0.x * C40.x + ns0.y * C40.y + ns0.z * C40.z + ns0.w * C40.w;

        float4 B41 = *(const float4*)&s_act[DIN + g1 * DS + lane16 * 4];
        float4 C41 = *(const float4*)&s_act[DIN + NG * DS + g1 * DS + lane16 * 4];
        float xh1 = s_act[h1 * HD + p1];
        float coef1 = s_dt[h1] * xh1;
        float dA1 = s_dA[h1];
        float4 ns1;
        ns1.x = sv1.x * dA1 + coef1 * B41.x;
        ns1.y = sv1.y * dA1 + coef1 * B41.y;
        ns1.z = sv1.z * dA1 + coef1 * B41.z;
        ns1.w = sv1.w * dA1 + coef1 * B41.w;
        __stcs((float4*)(out_ssm + base1), ns1);
        float part1 = ns1.x * C41.x + ns1.y * C41.y + ns1.z * C41.z + ns1.w * C41.w;

#pragma unroll
        for (int o = 8; o; o >>= 1) {
            part0 += __shfl_xor_sync(0xffffffffu, part0, o, 16);
            part1 += __shfl_xor_sync(0xffffffffu, part1, o, 16);
        }
        if (lane16 == 0) {
            s_y[rr0] = part0 + s_dp[h0] * xh0;
            s_y[rr1] = part1 + s_dp[h1] * xh1;
        }
    }
    __syncthreads();

    float lsum[4] = {0.f, 0.f, 0.f, 0.f};
#pragma unroll
    for (int k = 0; k < 8; k++) {
        int d = t + k * 256;
        float z = zx[d];
        float yv = s_y[d] * (z / (1.f + expf(-z)));
        s_y[d] = yv;
        lsum[k >> 1] += yv * yv;
    }
    int wid = t >> 5, lane = t & 31;
#pragma unroll
    for (int gg = 0; gg < NG; gg++) {
        float v = lsum[gg];
#pragma unroll
        for (int o = 16; o; o >>= 1) v += __shfl_xor_sync(0xffffffffu, v, o);
        if (lane == 0) s_part[wid][gg] = v;
    }
    __syncthreads();
    if (t < NG) {
        float a = 0.f;
        for (int w = 0; w < 8; w++) a += s_part[w][t];
        s_gsum[t] = a;
    }
    __syncthreads();
#pragma unroll
    for (int k = 0; k < 8; k++) {
        int d = t + k * 256;
        float scale = rsqrtf(s_gsum[k >> 1] * (1.f / 512.f) + EPS);
        g_y_h[(size_t)b * DIN + d] = __float2half_rn(s_y[d] * scale * norm_w[d]);
    }
}

// ---------------- launch ----------------------------------------------------
// stage = (BM+BN) rows * 128 B — same as tf32 version
#define SMEM_BIG3 (3 * (128 + 128) * 128)   // 98304
#define SMEM_MED3 (3 * (128 + 64) * 128)    // 73728
#define SMEM_SML3 (3 * (64 + 64) * 128)     // 49152

extern "C" void kernel_launch(void* const* d_in, const int* in_sizes, int n_in,
                              void* d_out, int out_size) {
    const float* frame_feat   = (const float*)d_in[0];
    const float* conv_state   = (const float*)d_in[1];
    const float* ssm_state    = (const float*)d_in[2];
    const float* ln_w         = (const float*)d_in[3];
    const float* ln_b         = (const float*)d_in[4];
    const float* w_in_gate    = (const float*)d_in[5];
    const float* b_in_gate    = (const float*)d_in[6];
    const float* w_input_proj = (const float*)d_in[7];
    const float* b_input_proj = (const float*)d_in[8];
    const float* w_in_proj    = (const float*)d_in[9];
    const float* conv_w       = (const float*)d_in[10];
    const float* conv_b       = (const float*)d_in[11];
    const float* A_log        = (const float*)d_in[12];
    const float* Dp           = (const float*)d_in[13];
    const float* dt_bias      = (const float*)d_in[14];
    const float* norm_w       = (const float*)d_in[15];
    const float* w_out_proj   = (const float*)d_in[16];
    const float* w_out_gate   = (const float*)d_in[17];
    const float* b_out_gate   = (const float*)d_in[18];
    const float* w_proj       = (const float*)d_in[19];
    const float* b_proj       = (const float*)d_in[20];

    float* out = (float*)d_out;
    float* out_clip = out;
    float* out_conv = out + (size_t)BATCH * CLIP_D;
    float* out_ssm = out_conv + (size_t)BATCH * CONV_DIM * DC;

    __half *p_wcat, *p_winp, *p_wop, *p_wog, *p_wpj;
    __half *p_xh, *p_gated_h, *p_yh, *p_opt_h, *p_ot_h;
    float *p_gated, *p_zx, *p_op;
    cudaGetSymbolAddress((void**)&p_wcat, g_wcat);
    cudaGetSymbolAddress((void**)&p_winp, g_winproj_h);
    cudaGetSymbolAddress((void**)&p_wop, g_woutproj_h);
    cudaGetSymbolAddress((void**)&p_wog, g_woutgate_h);
    cudaGetSymbolAddress((void**)&p_wpj, g_wproj_h);
    cudaGetSymbolAddress((void**)&p_xh, g_x_h);
    cudaGetSymbolAddress((void**)&p_gated, g_gated);
    cudaGetSymbolAddress((void**)&p_gated_h, g_gated_h);
    cudaGetSymbolAddress((void**)&p_zx, g_zx);
    cudaGetSymbolAddress((void**)&p_yh, g_y_h);
    cudaGetSymbolAddress((void**)&p_op, g_outpre);
    cudaGetSymbolAddress((void**)&p_opt_h, g_outpre_h);
    cudaGetSymbolAddress((void**)&p_ot_h, g_out_h);

    cudaFuncSetAttribute((mma_gemm<4, 128, 128, 4, 4, 8>), cudaFuncAttributeMaxDynamicSharedMemorySize, SMEM_BIG3);
    cudaFuncSetAttribute((mma_gemm<0, 128, 128, 4, 8, 4>), cudaFuncAttributeMaxDynamicSharedMemorySize, SMEM_BIG3);
    cudaFuncSetAttribute((mma_gemm<1, 128, 64, 2, 4, 8>), cudaFuncAttributeMaxDynamicSharedMemorySize, SMEM_MED3);
    cudaFuncSetAttribute((mma_gemm<2, 128, 64, 2, 4, 8>), cudaFuncAttributeMaxDynamicSharedMemorySize, SMEM_MED3);
    cudaFuncSetAttribute((mma_gemm<3, 64, 64, 2, 2, 8>), cudaFuncAttributeMaxDynamicSharedMemorySize, SMEM_SML3);

    // 0) LayerNorm (first blocks) + weight conversions, one launch
    prep_k<<<BATCH + CVT_BLOCKS, 256>>>((const float4*)w_input_proj,
                                        (const float4*)w_in_gate,
                                        (const float4*)w_in_proj,
                                        (const float4*)w_out_proj,
                                        (const float4*)w_out_gate,
                                        (const float4*)w_proj,
                                        frame_feat, ln_w, ln_b);

    // 2) gate pair GEMM (BIG tile, 8 warps), interleaved epilogue
    mma_gemm<4, 128, 128, 4, 4, 8><<<dim3(2048 / 128, BATCH / 128), 256, SMEM_BIG3>>>(
        p_xh, p_wcat, p_gated, p_gated_h, IN_DIM, 2048, b_input_proj, b_in_gate, nullptr);

    // 3) zx = gated @ w_in_proj^T (padded N) — BIG tile, 4 warps
    mma_gemm<0, 128, 128, 4, 8, 4><<<dim3(DINP_P / 128, BATCH / 128), 128, SMEM_BIG3>>>(
        p_gated_h, p_winp, p_zx, nullptr, HID, DINP_P, nullptr, nullptr, nullptr);

    // 4) conv + ssm + rmsnorm
    state_kernel<<<BATCH, 256>>>(conv_state, ssm_state, conv_w, conv_b,
                                 A_log, Dp, dt_bias, norm_w, out_conv, out_ssm);

    // 5) outpre = y @ w_out_proj^T + gated — MED tile, 8 warps
    mma_gemm<1, 128, 64, 2, 4, 8><<<dim3(HID / 64, BATCH / 128), 256, SMEM_MED3>>>(
        p_yh, p_wop, p_op, p_opt_h, DIN, HID, nullptr, nullptr, p_gated);

    // 6) out = outpre * sigmoid(outpre @ w_out_gate^T + b) — MED tile, 8 warps
    mma_gemm<2, 128, 64, 2, 4, 8><<<dim3(HID / 64, BATCH / 128), 256, SMEM_MED3>>>(
        p_opt_h, p_wog, nullptr, p_ot_h, HID, HID, b_out_gate, nullptr, p_op);

    // 7) clip = out @ w_proj^T + b — SML tile, 8 warps
    mma_gemm<3, 64, 64, 2, 2, 8><<<dim3(CLIP_D / 64, BATCH / 64), 256, SMEM_SML3>>>(
        p_ot_h, p_wpj, out_clip, nullptr, HID, CLIP_D, b_proj, nullptr, nullptr);
}